// round 16
// baseline (speedup 1.0000x reference)
#include <cuda_runtime.h>
#include <cuda_bf16.h>
#include <cuda_fp16.h>
#include <math.h>
#include <stdint.h>

#define T_TOK 2048
#define D_DIM 2048
#define N_H   16
#define N_KVH 4
#define HD    128
#define N_E   8
#define I_DIM 1024

// ---------------- scratch (static device globals; allocation-free) ----------------
__device__ float g_xnorm[T_TOK * D_DIM];
__device__ float g_q[T_TOK * N_H * HD];
__device__ float g_k[T_TOK * N_KVH * HD];
__device__ float g_v[T_TOK * N_KVH * HD];
__device__ float g_attn[T_TOK * N_H * HD];
__device__ float g_x2[T_TOK * D_DIM];
__device__ float g_gbuf[N_E * T_TOK * I_DIM];
__device__ float g_ubuf[N_E * T_TOK * I_DIM];
__device__ int   g_cnt[N_E];
__device__ int   g_tok[N_E * T_TOK];
__device__ float g_wt[N_E * T_TOK];
__device__ float g_cos[T_TOK * 64];
__device__ float g_sin[T_TOK * 64];

// ---------------- split/pack helpers ----------------
__device__ __forceinline__ uint32_t pack2bf(float x, float y, uint32_t& lo) {
    __nv_bfloat162 h2 = __floats2bfloat162_rn(x, y);
    float2 hf = __bfloat1622float2(h2);
    __nv_bfloat162 l2 = __floats2bfloat162_rn(x - hf.x, y - hf.y);
    lo = *reinterpret_cast<uint32_t*>(&l2);
    return *reinterpret_cast<uint32_t*>(&h2);
}
__device__ __forceinline__ uint32_t pack2h(float x, float y) {
    __half2 h2 = __floats2half2_rn(x, y);
    return *reinterpret_cast<uint32_t*>(&h2);
}
__device__ __forceinline__ uint32_t smem_u32(const void* p) {
    return (uint32_t)__cvta_generic_to_shared(p);
}

#define MMA_BF16(c0, c1, c2, c3, a0, a1, a2, a3, b0, b1)                         \
    asm volatile(                                                                \
        "mma.sync.aligned.m16n8k16.row.col.f32.bf16.bf16.f32 "                   \
        "{%0,%1,%2,%3}, {%4,%5,%6,%7}, {%8,%9}, {%0,%1,%2,%3};\n"                \
        : "+f"(c0), "+f"(c1), "+f"(c2), "+f"(c3)                                 \
        : "r"(a0), "r"(a1), "r"(a2), "r"(a3), "r"(b0), "r"(b1))

#define MMA_F16(c0, c1, c2, c3, a0, a1, a2, a3, b0, b1)                          \
    asm volatile(                                                                \
        "mma.sync.aligned.m16n8k16.row.col.f32.f16.f16.f32 "                     \
        "{%0,%1,%2,%3}, {%4,%5,%6,%7}, {%8,%9}, {%0,%1,%2,%3};\n"                \
        : "+f"(c0), "+f"(c1), "+f"(c2), "+f"(c3)                                 \
        : "r"(a0), "r"(a1), "r"(a2), "r"(a3), "r"(b0), "r"(b1))

#define LDSM4(r0, r1, r2, r3, a)                                                 \
    asm volatile("ldmatrix.sync.aligned.m8n8.x4.shared.b16 {%0,%1,%2,%3}, [%4];" \
                 : "=r"(r0), "=r"(r1), "=r"(r2), "=r"(r3) : "r"(a))

// ---------------- RMSNorm (plain) ----------------
__global__ void rmsnorm_kernel(const float* __restrict__ x, const float* __restrict__ w,
                               float* __restrict__ out) {
    int row = blockIdx.x, tid = threadIdx.x;
    const float4* xr = (const float4*)(x + (size_t)row * D_DIM);
    const float4* wr = (const float4*)w;
    float ss = 0.f;
#pragma unroll
    for (int p = 0; p < 2; ++p) {
        float4 v = xr[tid + p * 256];
        ss += v.x * v.x + v.y * v.y + v.z * v.z + v.w * v.w;
    }
#pragma unroll
    for (int o = 16; o; o >>= 1) ss += __shfl_xor_sync(0xffffffffu, ss, o);
    __shared__ float red[8];
    if ((tid & 31) == 0) red[tid >> 5] = ss;
    __syncthreads();
    float tot = 0.f;
#pragma unroll
    for (int i = 0; i < 8; ++i) tot += red[i];
    float inv = rsqrtf(tot * (1.0f / D_DIM) + 1e-6f);
    float4* o4 = (float4*)(out + (size_t)row * D_DIM);
#pragma unroll
    for (int p = 0; p < 2; ++p) {
        int i = tid + p * 256;
        float4 v = xr[i], wv = wr[i];
        o4[i] = make_float4(v.x * inv * wv.x, v.y * inv * wv.y,
                            v.z * inv * wv.z, v.w * inv * wv.w);
    }
}

// ---------------- RMSNorm-2 fused with router (logits inline, top2 scatter) ----------------
__global__ void rmsnorm_router_kernel(const float* __restrict__ x, const float* __restrict__ w,
                                      float* __restrict__ out, const float* __restrict__ gw,
                                      int* __restrict__ cnt, int* __restrict__ tok,
                                      float* __restrict__ wt) {
    int row = blockIdx.x, tid = threadIdx.x;
    const float4* xr = (const float4*)(x + (size_t)row * D_DIM);
    const float4* wr = (const float4*)w;
    float ss = 0.f;
#pragma unroll
    for (int p = 0; p < 2; ++p) {
        float4 v = xr[tid + p * 256];
        ss += v.x * v.x + v.y * v.y + v.z * v.z + v.w * v.w;
    }
#pragma unroll
    for (int o = 16; o; o >>= 1) ss += __shfl_xor_sync(0xffffffffu, ss, o);
    __shared__ float red[8];
    if ((tid & 31) == 0) red[tid >> 5] = ss;
    __syncthreads();
    float tot = 0.f;
#pragma unroll
    for (int i = 0; i < 8; ++i) tot += red[i];
    float inv = rsqrtf(tot * (1.0f / D_DIM) + 1e-6f);
    float4* o4 = (float4*)(out + (size_t)row * D_DIM);
    float racc[8] = {0, 0, 0, 0, 0, 0, 0, 0};
#pragma unroll
    for (int p = 0; p < 2; ++p) {
        int i = tid + p * 256;
        float4 v = xr[i], wv = wr[i];
        float4 r = make_float4(v.x * inv * wv.x, v.y * inv * wv.y,
                               v.z * inv * wv.z, v.w * inv * wv.w);
        o4[i] = r;
        const float* g0 = gw + (size_t)(4 * i) * N_E;
#pragma unroll
        for (int e = 0; e < 8; ++e)
            racc[e] += r.x * g0[e] + r.y * g0[8 + e] + r.z * g0[16 + e] + r.w * g0[24 + e];
    }
    __shared__ float smr[8][256];
#pragma unroll
    for (int e = 0; e < 8; ++e) smr[e][tid] = racc[e];
    __syncthreads();
    for (int s = 128; s; s >>= 1) {
        if (tid < s)
#pragma unroll
            for (int e = 0; e < 8; ++e) smr[e][tid] += smr[e][tid + s];
        __syncthreads();
    }
    if (tid == 0) {
        float l[8], p[8];
        float mx = -1e30f;
#pragma unroll
        for (int e = 0; e < 8; ++e) { l[e] = smr[e][0]; mx = fmaxf(mx, l[e]); }
        float ssum = 0.f;
#pragma unroll
        for (int e = 0; e < 8; ++e) { p[e] = expf(l[e] - mx); ssum += p[e]; }
#pragma unroll
        for (int e = 0; e < 8; ++e) p[e] /= ssum;
        int i0 = 0; float p0 = p[0];
#pragma unroll
        for (int e = 1; e < 8; ++e) if (p[e] > p0) { p0 = p[e]; i0 = e; }
        int i1 = -1; float p1 = -1.f;
#pragma unroll
        for (int e = 0; e < 8; ++e) if (e != i0 && p[e] > p1) { p1 = p[e]; i1 = e; }
        float wn = p0 + p1;
        int pos = atomicAdd(&cnt[i0], 1);
        tok[i0 * T_TOK + pos] = row; wt[i0 * T_TOK + pos] = p0 / wn;
        pos = atomicAdd(&cnt[i1], 1);
        tok[i1 * T_TOK + pos] = row; wt[i1 * T_TOK + pos] = p1 / wn;
    }
}

// ---------------- tensor-core GEMM (double-buffered, ldmatrix A-side) ----------------
// PREC: 0 = bf16x3 (emulated fp32), 1 = fp16 single MMA
// EPI: 0 = +bias store, 1 = +residual store, 2 = plain store, 3 = atomic scatter *weight
#define ALS 20
#define BPS 136
template <int EPI, bool GATHER, int NMAT, int PREC>
__global__ void __launch_bounds__(256, 2)
tgemm_kernel(const float* __restrict__ A,
             const float* __restrict__ Bm0, const float* __restrict__ Bm1,
             const float* __restrict__ Bm2,
             float* __restrict__ Cm0, float* __restrict__ Cm1, float* __restrict__ Cm2,
             const float* __restrict__ bi0, const float* __restrict__ bi1,
             const float* __restrict__ bi2,
             int M, int Kd, int N0a, int N1a, int N2a, int nb0, int nb1,
             const float* __restrict__ res,
             const int* __restrict__ cnt, const int* __restrict__ tok,
             const float* __restrict__ wt,
             long aBatch, long bBatch, long cBatch) {
    __shared__ uint32_t Ah[2][128 * ALS];
    __shared__ uint32_t Bh[2][16 * BPS];
    __shared__ uint32_t Al[2][PREC == 0 ? 128 * ALS : 1];
    __shared__ uint32_t Bl[2][PREC == 0 ? 16 * BPS : 1];
    const int e = blockIdx.z;
    const int Mcur = cnt ? cnt[e] : M;
    const int m0 = blockIdx.y * 128;
    if (m0 >= Mcur) return;
    int bx = blockIdx.x;
    const float* Bsel;
    float* Csel;
    const float* bsel;
    int N;
    if (NMAT == 1 || bx < nb0) {
        Bsel = Bm0; Csel = Cm0; bsel = bi0; N = N0a;
    } else if (NMAT == 2 || bx < nb0 + nb1) {
        bx -= nb0; Bsel = Bm1; Csel = Cm1; bsel = bi1; N = N1a;
    } else {
        bx -= nb0 + nb1; Bsel = Bm2; Csel = Cm2; bsel = bi2; N = N2a;
    }
    const int n0 = bx * 128;
    const float* Ab = A + (size_t)e * aBatch;
    const float* Bb = Bsel + (size_t)e * bBatch;
    float* Cb = Csel + (size_t)e * cBatch;
    const int* tokb = tok ? tok + e * T_TOK : nullptr;
    const int tid = threadIdx.x;
    const int lane = tid & 31, warp = tid >> 5;
    const int warp_m = (warp >> 2) * 64, warp_n = (warp & 3) * 32;
    const int gr = lane >> 2, gc = lane & 3;

    const int r0 = tid >> 3;
    const int ac4 = (tid & 7) << 2;
    const int akp0 = (tid & 7) << 1;
    int arow[4];
    bool av[4];
#pragma unroll
    for (int p = 0; p < 4; ++p) {
        int rg = m0 + r0 + p * 32;
        av[p] = rg < Mcur;
        arow[p] = av[p] ? (GATHER ? tokb[rg] : rg) : 0;
    }
    const int bkp = tid >> 5;
    const int bc4 = (tid & 31) << 2;

    const uint32_t ahBase = smem_u32(&Ah[0][0]);
    const uint32_t alBase = (PREC == 0) ? smem_u32(&Al[0][0]) : 0;
    const int laneA = (warp_m + (lane & 15)) * ALS + ((lane >> 4) << 2);

    float acc[4][4][4];
#pragma unroll
    for (int mt = 0; mt < 4; ++mt)
#pragma unroll
        for (int nt = 0; nt < 4; ++nt)
#pragma unroll
            for (int r = 0; r < 4; ++r) acc[mt][nt][r] = 0.f;

    float4 aReg[4], bReg[4];
#define LDG_TILE(KOFF)                                                              \
    do {                                                                            \
        _Pragma("unroll")                                                           \
        for (int p = 0; p < 4; ++p)                                                 \
            aReg[p] = av[p] ? *(const float4*)(Ab + (size_t)arow[p] * Kd + (KOFF) + ac4) \
                            : make_float4(0.f, 0.f, 0.f, 0.f);                      \
        _Pragma("unroll")                                                           \
        for (int p = 0; p < 2; ++p) {                                               \
            const float* brow = Bb + (size_t)((KOFF) + 2 * (bkp + p * 8)) * N + n0 + bc4; \
            bReg[2 * p] = *(const float4*)brow;                                     \
            bReg[2 * p + 1] = *(const float4*)(brow + N);                           \
        }                                                                           \
    } while (0)

#define STS_TILE(ST)                                                                \
    do {                                                                            \
        _Pragma("unroll")                                                           \
        for (int p = 0; p < 4; ++p) {                                               \
            int row = r0 + p * 32;                                                  \
            if (PREC == 0) {                                                        \
                uint32_t l0, l1;                                                    \
                uint32_t h0 = pack2bf(aReg[p].x, aReg[p].y, l0);                    \
                uint32_t h1 = pack2bf(aReg[p].z, aReg[p].w, l1);                    \
                *(uint2*)&Ah[ST][row * ALS + akp0] = make_uint2(h0, h1);            \
                *(uint2*)&Al[ST][row * ALS + akp0] = make_uint2(l0, l1);            \
            } else {                                                                \
                *(uint2*)&Ah[ST][row * ALS + akp0] =                                \
                    make_uint2(pack2h(aReg[p].x, aReg[p].y),                        \
                               pack2h(aReg[p].z, aReg[p].w));                       \
            }                                                                       \
        }                                                                           \
        _Pragma("unroll")                                                           \
        for (int p = 0; p < 2; ++p) {                                               \
            int kp = bkp + p * 8;                                                   \
            float4 v0 = bReg[2 * p], v1 = bReg[2 * p + 1];                          \
            if (PREC == 0) {                                                        \
                uint32_t h0, h1, h2, h3, l0, l1, l2, l3;                            \
                h0 = pack2bf(v0.x, v1.x, l0);                                       \
                h1 = pack2bf(v0.y, v1.y, l1);                                       \
                h2 = pack2bf(v0.z, v1.z, l2);                                       \
                h3 = pack2bf(v0.w, v1.w, l3);                                       \
                *(uint4*)&Bh[ST][kp * BPS + bc4] = make_uint4(h0, h1, h2, h3);      \
                *(uint4*)&Bl[ST][kp * BPS + bc4] = make_uint4(l0, l1, l2, l3);      \
            } else {                                                                \
                *(uint4*)&Bh[ST][kp * BPS + bc4] = make_uint4(                      \
                    pack2h(v0.x, v1.x), pack2h(v0.y, v1.y),                         \
                    pack2h(v0.z, v1.z), pack2h(v0.w, v1.w));                        \
            }                                                                       \
        }                                                                           \
    } while (0)

    LDG_TILE(0);
    STS_TILE(0);
    __syncthreads();

    const int nTiles = Kd >> 5;
    for (int t = 0; t < nTiles; ++t) {
        const int cur = t & 1, nxt = cur ^ 1;
        const uint32_t aOff = (uint32_t)cur * (128 * ALS * 4);
        if (t + 1 < nTiles) LDG_TILE((t + 1) << 5);
#pragma unroll
        for (int s = 0; s < 2; ++s) {
            const int kpb = s * 8;
            uint32_t ah[4][4];
#pragma unroll
            for (int mt = 0; mt < 4; ++mt) {
                uint32_t addr = ahBase + aOff + ((laneA + mt * 16 * ALS + kpb) << 2);
                LDSM4(ah[mt][0], ah[mt][1], ah[mt][2], ah[mt][3], addr);
            }
            uint32_t bh[4][2];
#pragma unroll
            for (int nt = 0; nt < 4; ++nt) {
                int n = warp_n + nt * 8 + gr;
                bh[nt][0] = Bh[cur][(kpb + gc) * BPS + n];
                bh[nt][1] = Bh[cur][(kpb + gc + 4) * BPS + n];
            }
            if (PREC == 0) {
                uint32_t al[4][4], bl[4][2];
#pragma unroll
                for (int mt = 0; mt < 4; ++mt) {
                    uint32_t addr = alBase + aOff + ((laneA + mt * 16 * ALS + kpb) << 2);
                    LDSM4(al[mt][0], al[mt][1], al[mt][2], al[mt][3], addr);
                }
#pragma unroll
                for (int nt = 0; nt < 4; ++nt) {
                    int n = warp_n + nt * 8 + gr;
                    bl[nt][0] = Bl[cur][(kpb + gc) * BPS + n];
                    bl[nt][1] = Bl[cur][(kpb + gc + 4) * BPS + n];
                }
#pragma unroll
                for (int mt = 0; mt < 4; ++mt)
#pragma unroll
                    for (int nt = 0; nt < 4; ++nt) {
                        float* c = acc[mt][nt];
                        MMA_BF16(c[0], c[1], c[2], c[3],
                                 ah[mt][0], ah[mt][1], ah[mt][2], ah[mt][3],
                                 bl[nt][0], bl[nt][1]);
                        MMA_BF16(c[0], c[1], c[2], c[3],
                                 al[mt][0], al[mt][1], al[mt][2], al[mt][3],
                                 bh[nt][0], bh[nt][1]);
                        MMA_BF16(c[0], c[1], c[2], c[3],
                                 ah[mt][0], ah[mt][1], ah[mt][2], ah[mt][3],
                                 bh[nt][0], bh[nt][1]);
                    }
            } else {
#pragma unroll
                for (int mt = 0; mt < 4; ++mt)
#pragma unroll
                    for (int nt = 0; nt < 4; ++nt) {
                        float* c = acc[mt][nt];
                        MMA_F16(c[0], c[1], c[2], c[3],
                                ah[mt][0], ah[mt][1], ah[mt][2], ah[mt][3],
                                bh[nt][0], bh[nt][1]);
                    }
            }
        }
        if (t + 1 < nTiles) {
            STS_TILE(nxt);
            __syncthreads();
        }
    }
#undef LDG_TILE
#undef STS_TILE

#pragma unroll
    for (int mt = 0; mt < 4; ++mt) {
#pragma unroll
        for (int rr = 0; rr < 2; ++rr) {
            int rg = m0 + warp_m + mt * 16 + gr + rr * 8;
            if (rg >= Mcur) continue;
            if (EPI == 3) {
                int t2 = tokb[rg];
                float w = wt[e * T_TOK + rg];
                float* outr = Cm0 + (size_t)t2 * N;
#pragma unroll
                for (int nt = 0; nt < 4; ++nt) {
                    int cb = n0 + warp_n + nt * 8 + gc * 2;
                    atomicAdd(&outr[cb], acc[mt][nt][rr * 2] * w);
                    atomicAdd(&outr[cb + 1], acc[mt][nt][rr * 2 + 1] * w);
                }
            } else {
#pragma unroll
                for (int nt = 0; nt < 4; ++nt) {
                    int cb = n0 + warp_n + nt * 8 + gc * 2;
                    float v0 = acc[mt][nt][rr * 2], v1 = acc[mt][nt][rr * 2 + 1];
                    if (EPI == 0) { v0 += bsel[cb]; v1 += bsel[cb + 1]; }
                    if (EPI == 1) {
                        const float* rrow = res + (size_t)rg * N;
                        v0 += rrow[cb]; v1 += rrow[cb + 1];
                    }
                    *(float2*)(Cb + (size_t)rg * N + cb) = make_float2(v0, v1);
                }
            }
        }
    }
}

// ---------------- RoPE ----------------
__global__ void rope_table_kernel(const int* __restrict__ pos,
                                  float* __restrict__ ctab, float* __restrict__ stab) {
    int t = blockIdx.x, i = threadIdx.x;
    float p = (float)pos[t];
    float invf = (float)exp(-(double)i * (13.815510557964274 / 64.0));
    float fr = p * invf;
    double d = (double)fr;
    double n = rint(d * 0.15915494309189535);
    float r = (float)(d - n * 6.283185307179586);
    float s, c;
    sincosf(r, &s, &c);
    ctab[t * 64 + i] = c;
    stab[t * 64 + i] = s;
}

__global__ void rope_apply_kernel(float* __restrict__ q, float* __restrict__ k,
                                  const float* __restrict__ ctab,
                                  const float* __restrict__ stab) {
    int t = blockIdx.x, tid = threadIdx.x;
    __shared__ float cs[64], sn[64];
    if (tid < 64) {
        cs[tid] = ctab[t * 64 + tid];
        sn[tid] = stab[t * 64 + tid];
    }
    __syncthreads();
    for (int idx = tid; idx < (N_H + N_KVH) * 64; idx += 256) {
        int h = idx >> 6, i = idx & 63;
        float* b = (h < N_H) ? (q + ((size_t)t * N_H + h) * HD)
                             : (k + ((size_t)t * N_KVH + (h - N_H)) * HD);
        float c = cs[i], s = sn[i];
        float x1 = b[i], x2 = b[i + 64];
        b[i] = x1 * c - x2 * s;
        b[i + 64] = x2 * c + x1 * s;
    }
}

// ---------------- flash attention v5 (bf16x3, ldmatrix; 1 CTA/SM — regs unconstrained) ----------------
#define QLS 68
#define PLS 36
#define VPS 132
#define SST 68
__global__ void __launch_bounds__(256)
flash5_kernel(const float* __restrict__ q, const float* __restrict__ k,
              const float* __restrict__ v, float* __restrict__ o) {
    extern __shared__ uint32_t sm5[];
    uint32_t* Qh = sm5;
    uint32_t* Ql = Qh + 64 * QLS;
    uint32_t* Kh = Ql + 64 * QLS;
    uint32_t* Kl = Kh + 64 * QLS;
    float* Ss = (float*)(Kl + 64 * QLS);
    uint32_t* Ph = (uint32_t*)(Ss + 64 * SST);
    uint32_t* Pl = Ph + 64 * PLS;
    float* salpha = (float*)(Pl + 64 * PLS);
    const int tid = threadIdx.x;
    const int lane = tid & 31, warp = tid >> 5;
    const int gr = lane >> 2, gc = lane & 3;
    const int wms = (warp >> 1) * 16;
    const int wns = (warp & 1) * 32;
    const int wno = (warp & 1) * 64;
    const int sr = tid >> 2, sg = tid & 3;
    const int qt = blockIdx.x, head = blockIdx.y, kvh = head >> 2;
    const int qr0 = qt * 64;
    const float scale = 0.08838834764831845f;

    const uint32_t qhBase = smem_u32(Qh), qlBase = smem_u32(Ql);
    const uint32_t phBase = smem_u32(Ph), plBase = smem_u32(Pl);
    const int laneQ = (wms + (lane & 15)) * QLS + ((lane >> 4) << 2);
    const int laneP = (wms + (lane & 15)) * PLS + ((lane >> 4) << 2);

#pragma unroll
    for (int p = 0; p < 8; ++p) {
        int idx = tid + p * 256;
        int row = idx >> 5, c4 = (idx & 31) << 2;
        float4 vq = *(const float4*)(q + (size_t)(qr0 + row) * (N_H * HD) + head * HD + c4);
        int dp = c4 >> 1;
        uint32_t l0, l1;
        uint32_t h0 = pack2bf(vq.x, vq.y, l0);
        uint32_t h1 = pack2bf(vq.z, vq.w, l1);
        *(uint2*)&Qh[row * QLS + dp] = make_uint2(h0, h1);
        *(uint2*)&Ql[row * QLS + dp] = make_uint2(l0, l1);
    }
    float oacc[8][4];
#pragma unroll
    for (int nt = 0; nt < 8; ++nt)
#pragma unroll
        for (int r = 0; r < 4; ++r) oacc[nt][r] = 0.f;
    float mrow = -INFINITY, lrow = 0.f;

    for (int kt = 0; kt <= qt; ++kt) {
        const int kr0 = kt * 64;
        __syncthreads();
#pragma unroll
        for (int p = 0; p < 8; ++p) {
            int idx = tid + p * 256;
            int key = idx >> 5, c4 = (idx & 31) << 2;
            float4 vk = *(const float4*)(k + (size_t)(kr0 + key) * (N_KVH * HD) + kvh * HD + c4);
            int dp = c4 >> 1;
            uint32_t l0, l1;
            uint32_t h0 = pack2bf(vk.x, vk.y, l0);
            uint32_t h1 = pack2bf(vk.z, vk.w, l1);
            *(uint2*)&Kh[key * QLS + dp] = make_uint2(h0, h1);
            *(uint2*)&Kl[key * QLS + dp] = make_uint2(l0, l1);
        }
        __syncthreads();
        float sc[4][4];
#pragma unroll
        for (int nt = 0; nt < 4; ++nt)
#pragma unroll
            for (int r = 0; r < 4; ++r) sc[nt][r] = 0.f;
#pragma unroll
        for (int ks = 0; ks < 8; ++ks) {
            const int kpb = ks * 8;
            uint32_t ah[4], al[4];
            LDSM4(ah[0], ah[1], ah[2], ah[3], qhBase + ((laneQ + kpb) << 2));
            LDSM4(al[0], al[1], al[2], al[3], qlBase + ((laneQ + kpb) << 2));
#pragma unroll
            for (int nt = 0; nt < 4; ++nt) {
                int n = wns + nt * 8 + gr;
                uint32_t bh0 = Kh[n * QLS + kpb + gc];
                uint32_t bh1 = Kh[n * QLS + kpb + gc + 4];
                uint32_t bl0 = Kl[n * QLS + kpb + gc];
                uint32_t bl1 = Kl[n * QLS + kpb + gc + 4];
                float* c = sc[nt];
                MMA_BF16(c[0], c[1], c[2], c[3], ah[0], ah[1], ah[2], ah[3], bl0, bl1);
                MMA_BF16(c[0], c[1], c[2], c[3], al[0], al[1], al[2], al[3], bh0, bh1);
                MMA_BF16(c[0], c[1], c[2], c[3], ah[0], ah[1], ah[2], ah[3], bh0, bh1);
            }
        }
#pragma unroll
        for (int nt = 0; nt < 4; ++nt) {
            int cb = wns + nt * 8 + gc * 2;
            *(float2*)&Ss[(wms + gr) * SST + cb] = make_float2(sc[nt][0], sc[nt][1]);
            *(float2*)&Ss[(wms + gr + 8) * SST + cb] = make_float2(sc[nt][2], sc[nt][3]);
        }
        __syncthreads();
#pragma unroll
        for (int p = 0; p < 4; ++p) {
            int idx = tid + p * 256;
            int kp = idx >> 5, c4 = (idx & 31) << 2;
            const float* vrow = v + (size_t)(kr0 + 2 * kp) * (N_KVH * HD) + kvh * HD + c4;
            float4 v0 = *(const float4*)vrow;
            float4 v1 = *(const float4*)(vrow + N_KVH * HD);
            uint32_t h0, h1, h2, h3, l0, l1, l2, l3;
            h0 = pack2bf(v0.x, v1.x, l0);
            h1 = pack2bf(v0.y, v1.y, l1);
            h2 = pack2bf(v0.z, v1.z, l2);
            h3 = pack2bf(v0.w, v1.w, l3);
            *(uint4*)&Kh[kp * VPS + c4] = make_uint4(h0, h1, h2, h3);
            *(uint4*)&Kl[kp * VPS + c4] = make_uint4(l0, l1, l2, l3);
        }
        {
            float s[16];
#pragma unroll
            for (int jj = 0; jj < 16; ++jj) s[jj] = Ss[sr * SST + sg * 16 + jj];
            float mx = -INFINITY;
#pragma unroll
            for (int jj = 0; jj < 16; ++jj) {
                int col = kr0 + sg * 16 + jj;
                float sv = (col <= qr0 + sr) ? s[jj] * scale : -INFINITY;
                s[jj] = sv;
                mx = fmaxf(mx, sv);
            }
            mx = fmaxf(mx, __shfl_xor_sync(0xffffffffu, mx, 1));
            mx = fmaxf(mx, __shfl_xor_sync(0xffffffffu, mx, 2));
            float nm = fmaxf(mrow, mx);
            float rs = 0.f;
#pragma unroll
            for (int jj = 0; jj < 16; ++jj) {
                s[jj] = expf(s[jj] - nm);
                rs += s[jj];
            }
#pragma unroll
            for (int qq = 0; qq < 8; ++qq) {
                uint32_t lo;
                uint32_t hi = pack2bf(s[2 * qq], s[2 * qq + 1], lo);
                Ph[sr * PLS + sg * 8 + qq] = hi;
                Pl[sr * PLS + sg * 8 + qq] = lo;
            }
            rs += __shfl_xor_sync(0xffffffffu, rs, 1);
            rs += __shfl_xor_sync(0xffffffffu, rs, 2);
            float alpha = expf(mrow - nm);
            lrow = lrow * alpha + rs;
            mrow = nm;
            if (sg == 0) salpha[sr] = alpha;
        }
        __syncthreads();
        {
            float a0 = salpha[wms + gr], a1 = salpha[wms + gr + 8];
#pragma unroll
            for (int nt = 0; nt < 8; ++nt) {
                oacc[nt][0] *= a0; oacc[nt][1] *= a0;
                oacc[nt][2] *= a1; oacc[nt][3] *= a1;
            }
        }
#pragma unroll
        for (int ks = 0; ks < 4; ++ks) {
            const int kpb = ks * 8;
            uint32_t ah[4], al[4];
            LDSM4(ah[0], ah[1], ah[2], ah[3], phBase + ((laneP + kpb) << 2));
            LDSM4(al[0], al[1], al[2], al[3], plBase + ((laneP + kpb) << 2));
#pragma unroll
            for (int nt = 0; nt < 8; ++nt) {
                int n = wno + nt * 8 + gr;
                uint32_t bh0 = Kh[(kpb + gc) * VPS + n];
                uint32_t bh1 = Kh[(kpb + gc + 4) * VPS + n];
                uint32_t bl0 = Kl[(kpb + gc) * VPS + n];
                uint32_t bl1 = Kl[(kpb + gc + 4) * VPS + n];
                float* c = oacc[nt];
                MMA_BF16(c[0], c[1], c[2], c[3], ah[0], ah[1], ah[2], ah[3], bl0, bl1);
                MMA_BF16(c[0], c[1], c[2], c[3], al[0], al[1], al[2], al[3], bh0, bh1);
                MMA_BF16(c[0], c[1], c[2], c[3], ah[0], ah[1], ah[2], ah[3], bh0, bh1);
            }
        }
    }
    __syncthreads();
    if (sg == 0) salpha[sr] = 1.f / lrow;
    __syncthreads();
    float i0 = salpha[wms + gr], i1 = salpha[wms + gr + 8];
#pragma unroll
    for (int nt = 0; nt < 8; ++nt) {
        int cb = head * HD + wno + nt * 8 + gc * 2;
        *(float2*)(o + (size_t)(qr0 + wms + gr) * (N_H * HD) + cb) =
            make_float2(oacc[nt][0] * i0, oacc[nt][1] * i0);
        *(float2*)(o + (size_t)(qr0 + wms + gr + 8) * (N_H * HD) + cb) =
            make_float2(oacc[nt][2] * i1, oacc[nt][3] * i1);
    }
}

// ---------------- silu(g)*u, only over active rows per expert ----------------
__global__ void silu_mul_kernel(float* __restrict__ g, const float* __restrict__ u,
                                const int* __restrict__ cnt) {
    int e = blockIdx.z;
    int row = blockIdx.y;
    if (row >= cnt[e]) return;
    size_t base = ((size_t)e * T_TOK + row) * I_DIM;
    int i = blockIdx.x * 256 + threadIdx.x;
    float4 gv = ((const float4*)(g + base))[i];
    float4 uv = ((const float4*)(u + base))[i];
    gv.x = gv.x / (1.f + __expf(-gv.x)) * uv.x;
    gv.y = gv.y / (1.f + __expf(-gv.y)) * uv.y;
    gv.z = gv.z / (1.f + __expf(-gv.z)) * uv.z;
    gv.w = gv.w / (1.f + __expf(-gv.w)) * uv.w;
    ((float4*)(g + base))[i] = gv;
}

// ---------------- launch ----------------
extern "C" void kernel_launch(void* const* d_in, const int* in_sizes, int n_in,
                              void* d_out, int out_size) {
    const float* hidden = (const float*)d_in[0];
    const int* positions = (const int*)d_in[1];
    const float* ln1 = (const float*)d_in[2];
    const float* ln2 = (const float*)d_in[3];
    const float* wq = (const float*)d_in[4];
    const float* bq = (const float*)d_in[5];
    const float* wk = (const float*)d_in[6];
    const float* bk = (const float*)d_in[7];
    const float* wv = (const float*)d_in[8];
    const float* bv = (const float*)d_in[9];
    const float* wo = (const float*)d_in[10];
    const float* gate_w = (const float*)d_in[11];
    const float* w_gate = (const float*)d_in[12];
    const float* w_up = (const float*)d_in[13];
    const float* w_down = (const float*)d_in[14];
    float* out = (float*)d_out;

    float *xnorm, *q, *k, *v, *attn, *x2, *gbuf, *ubuf, *wt, *ctab, *stab;
    int *cnt, *tok;
    cudaGetSymbolAddress((void**)&xnorm, g_xnorm);
    cudaGetSymbolAddress((void**)&q, g_q);
    cudaGetSymbolAddress((void**)&k, g_k);
    cudaGetSymbolAddress((void**)&v, g_v);
    cudaGetSymbolAddress((void**)&attn, g_attn);
    cudaGetSymbolAddress((void**)&x2, g_x2);
    cudaGetSymbolAddress((void**)&gbuf, g_gbuf);
    cudaGetSymbolAddress((void**)&ubuf, g_ubuf);
    cudaGetSymbolAddress((void**)&cnt, g_cnt);
    cudaGetSymbolAddress((void**)&tok, g_tok);
    cudaGetSymbolAddress((void**)&wt, g_wt);
    cudaGetSymbolAddress((void**)&ctab, g_cos);
    cudaGetSymbolAddress((void**)&stab, g_sin);

    const int smem_f5 = (4 * 64 * QLS + 64 * SST + 2 * 64 * PLS + 64) * 4;
    cudaFuncSetAttribute(flash5_kernel, cudaFuncAttributeMaxDynamicSharedMemorySize, smem_f5);

    // 0) RoPE table
    rope_table_kernel<<<T_TOK, 64>>>(positions, ctab, stab);
    // 1) RMSNorm 1
    rmsnorm_kernel<<<T_TOK, 256>>>(hidden, ln1, xnorm);
    // 2) fused QKV projection (+bias): bf16x3
    tgemm_kernel<0, false, 3, 0><<<dim3(24, 16, 1), 256>>>(
        xnorm, wq, wk, wv, q, k, v, bq, bk, bv,
        T_TOK, D_DIM, 2048, 512, 512, 16, 4,
        nullptr, nullptr, nullptr, nullptr, 0, 0, 0);
    // 3) RoPE apply (one block per token)
    rope_apply_kernel<<<T_TOK, 256>>>(q, k, ctab, stab);
    // 4) attention (bf16x3, ldmatrix)
    flash5_kernel<<<dim3(T_TOK / 64, N_H), 256, smem_f5>>>(q, k, v, attn);
    // 5) output proj + residual: bf16x3
    tgemm_kernel<1, false, 1, 0><<<dim3(16, 16, 1), 256>>>(
        attn, wo, nullptr, nullptr, out, nullptr, nullptr, nullptr, nullptr, nullptr,
        T_TOK, 2048, 2048, 0, 0, 16, 0,
        hidden, nullptr, nullptr, nullptr, 0, 0, 0);
    // 6+7) RMSNorm 2 fused with router
    cudaMemsetAsync(cnt, 0, N_E * sizeof(int));
    rmsnorm_router_kernel<<<T_TOK, 256>>>(out, ln2, x2, gate_w, cnt, tok, wt);
    // 8) expert gate+up fused: fp16 single-MMA
    tgemm_kernel<2, true, 2, 1><<<dim3(16, 16, N_E), 256>>>(
        x2, w_gate, w_up, nullptr, gbuf, ubuf, nullptr, nullptr, nullptr, nullptr,
        0, D_DIM, 1024, 1024, 0, 8, 8,
        nullptr, cnt, tok, nullptr, 0, (long)D_DIM * I_DIM, (long)T_TOK * I_DIM);
    // 9) silu(g)*u on active rows only
    silu_mul_kernel<<<dim3(1, T_TOK, N_E), 256>>>(gbuf, ubuf, cnt);
    // 10) expert down GEMM: fp16 single-MMA, scatter *weight into d_out
    tgemm_kernel<3, false, 1, 1><<<dim3(16, 16, N_E), 256>>>(
        gbuf, w_down, nullptr, nullptr, out, nullptr, nullptr, nullptr, nullptr, nullptr,
        0, I_DIM, 2048, 0, 0, 16, 0,
        nullptr, cnt, tok, wt, (long)T_TOK * I_DIM, (long)I_DIM * D_DIM, 0);
}

// round 17
// speedup vs baseline: 1.0971x; 1.0971x over previous
#include <cuda_runtime.h>
#include <cuda_bf16.h>
#include <cuda_fp16.h>
#include <math.h>
#include <stdint.h>

#define T_TOK 2048
#define D_DIM 2048
#define N_H   16
#define N_KVH 4
#define HD    128
#define N_E   8
#define I_DIM 1024

// ---------------- scratch (static device globals; allocation-free) ----------------
__device__ float g_xnorm[T_TOK * D_DIM];
__device__ float g_q[T_TOK * N_H * HD];
__device__ float g_k[T_TOK * N_KVH * HD];
__device__ float g_v[T_TOK * N_KVH * HD];
__device__ float g_attn[T_TOK * N_H * HD];
__device__ float g_x2[T_TOK * D_DIM];
__device__ float g_gbuf[N_E * T_TOK * I_DIM];
__device__ float g_ubuf[N_E * T_TOK * I_DIM];
__device__ int   g_cnt[N_E];
__device__ int   g_tok[N_E * T_TOK];
__device__ float g_wt[N_E * T_TOK];

// ---------------- split/pack helpers ----------------
__device__ __forceinline__ uint32_t pack2bf(float x, float y, uint32_t& lo) {
    __nv_bfloat162 h2 = __floats2bfloat162_rn(x, y);
    float2 hf = __bfloat1622float2(h2);
    __nv_bfloat162 l2 = __floats2bfloat162_rn(x - hf.x, y - hf.y);
    lo = *reinterpret_cast<uint32_t*>(&l2);
    return *reinterpret_cast<uint32_t*>(&h2);
}
__device__ __forceinline__ uint32_t pack2h(float x, float y) {
    __half2 h2 = __floats2half2_rn(x, y);
    return *reinterpret_cast<uint32_t*>(&h2);
}
__device__ __forceinline__ uint32_t smem_u32(const void* p) {
    return (uint32_t)__cvta_generic_to_shared(p);
}

#define MMA_BF16(c0, c1, c2, c3, a0, a1, a2, a3, b0, b1)                         \
    asm volatile(                                                                \
        "mma.sync.aligned.m16n8k16.row.col.f32.bf16.bf16.f32 "                   \
        "{%0,%1,%2,%3}, {%4,%5,%6,%7}, {%8,%9}, {%0,%1,%2,%3};\n"                \
        : "+f"(c0), "+f"(c1), "+f"(c2), "+f"(c3)                                 \
        : "r"(a0), "r"(a1), "r"(a2), "r"(a3), "r"(b0), "r"(b1))

#define MMA_F16(c0, c1, c2, c3, a0, a1, a2, a3, b0, b1)                          \
    asm volatile(                                                                \
        "mma.sync.aligned.m16n8k16.row.col.f32.f16.f16.f32 "                     \
        "{%0,%1,%2,%3}, {%4,%5,%6,%7}, {%8,%9}, {%0,%1,%2,%3};\n"                \
        : "+f"(c0), "+f"(c1), "+f"(c2), "+f"(c3)                                 \
        : "r"(a0), "r"(a1), "r"(a2), "r"(a3), "r"(b0), "r"(b1))

#define LDSM4(r0, r1, r2, r3, a)                                                 \
    asm volatile("ldmatrix.sync.aligned.m8n8.x4.shared.b16 {%0,%1,%2,%3}, [%4];" \
                 : "=r"(r0), "=r"(r1), "=r"(r2), "=r"(r3) : "r"(a))

// ---------------- RMSNorm ----------------
__global__ void rmsnorm_kernel(const float* __restrict__ x, const float* __restrict__ w,
                               float* __restrict__ out) {
    int row = blockIdx.x, tid = threadIdx.x;
    const float4* xr = (const float4*)(x + (size_t)row * D_DIM);
    const float4* wr = (const float4*)w;
    float ss = 0.f;
#pragma unroll
    for (int p = 0; p < 2; ++p) {
        float4 v = xr[tid + p * 256];
        ss += v.x * v.x + v.y * v.y + v.z * v.z + v.w * v.w;
    }
#pragma unroll
    for (int o = 16; o; o >>= 1) ss += __shfl_xor_sync(0xffffffffu, ss, o);
    __shared__ float red[8];
    if ((tid & 31) == 0) red[tid >> 5] = ss;
    __syncthreads();
    float tot = 0.f;
#pragma unroll
    for (int i = 0; i < 8; ++i) tot += red[i];
    float inv = rsqrtf(tot * (1.0f / D_DIM) + 1e-6f);
    float4* o4 = (float4*)(out + (size_t)row * D_DIM);
#pragma unroll
    for (int p = 0; p < 2; ++p) {
        int i = tid + p * 256;
        float4 v = xr[i], wv = wr[i];
        o4[i] = make_float4(v.x * inv * wv.x, v.y * inv * wv.y,
                            v.z * inv * wv.z, v.w * inv * wv.w);
    }
}

// ---------------- tensor-core GEMM (double-buffered, ldmatrix A-side) ----------------
// PREC: 0 = bf16x3 (emulated fp32), 1 = fp16 single MMA
// EPI: 0 = +bias store, 1 = +residual store, 2 = plain store, 3 = atomic scatter *weight
#define ALS 20
#define BPS 136
template <int EPI, bool GATHER, int NMAT, int PREC>
__global__ void __launch_bounds__(256, 2)
tgemm_kernel(const float* __restrict__ A,
             const float* __restrict__ Bm0, const float* __restrict__ Bm1,
             const float* __restrict__ Bm2,
             float* __restrict__ Cm0, float* __restrict__ Cm1, float* __restrict__ Cm2,
             const float* __restrict__ bi0, const float* __restrict__ bi1,
             const float* __restrict__ bi2,
             int M, int Kd, int N0a, int N1a, int N2a, int nb0, int nb1,
             const float* __restrict__ res,
             const int* __restrict__ cnt, const int* __restrict__ tok,
             const float* __restrict__ wt,
             long aBatch, long bBatch, long cBatch) {
    __shared__ uint32_t Ah[2][128 * ALS];
    __shared__ uint32_t Bh[2][16 * BPS];
    __shared__ uint32_t Al[2][PREC == 0 ? 128 * ALS : 1];
    __shared__ uint32_t Bl[2][PREC == 0 ? 16 * BPS : 1];
    const int e = blockIdx.z;
    const int Mcur = cnt ? cnt[e] : M;
    const int m0 = blockIdx.y * 128;
    if (m0 >= Mcur) return;
    int bx = blockIdx.x;
    const float* Bsel;
    float* Csel;
    const float* bsel;
    int N;
    if (NMAT == 1 || bx < nb0) {
        Bsel = Bm0; Csel = Cm0; bsel = bi0; N = N0a;
    } else if (NMAT == 2 || bx < nb0 + nb1) {
        bx -= nb0; Bsel = Bm1; Csel = Cm1; bsel = bi1; N = N1a;
    } else {
        bx -= nb0 + nb1; Bsel = Bm2; Csel = Cm2; bsel = bi2; N = N2a;
    }
    const int n0 = bx * 128;
    const float* Ab = A + (size_t)e * aBatch;
    const float* Bb = Bsel + (size_t)e * bBatch;
    float* Cb = Csel + (size_t)e * cBatch;
    const int* tokb = tok ? tok + e * T_TOK : nullptr;
    const int tid = threadIdx.x;
    const int lane = tid & 31, warp = tid >> 5;
    const int warp_m = (warp >> 2) * 64, warp_n = (warp & 3) * 32;
    const int gr = lane >> 2, gc = lane & 3;

    const int r0 = tid >> 3;
    const int ac4 = (tid & 7) << 2;
    const int akp0 = (tid & 7) << 1;
    int arow[4];
    bool av[4];
#pragma unroll
    for (int p = 0; p < 4; ++p) {
        int rg = m0 + r0 + p * 32;
        av[p] = rg < Mcur;
        arow[p] = av[p] ? (GATHER ? tokb[rg] : rg) : 0;
    }
    const int bkp = tid >> 5;
    const int bc4 = (tid & 31) << 2;

    const uint32_t ahBase = smem_u32(&Ah[0][0]);
    const uint32_t alBase = (PREC == 0) ? smem_u32(&Al[0][0]) : 0;
    const int laneA = (warp_m + (lane & 15)) * ALS + ((lane >> 4) << 2);

    float acc[4][4][4];
#pragma unroll
    for (int mt = 0; mt < 4; ++mt)
#pragma unroll
        for (int nt = 0; nt < 4; ++nt)
#pragma unroll
            for (int r = 0; r < 4; ++r) acc[mt][nt][r] = 0.f;

    float4 aReg[4], bReg[4];
#define LDG_TILE(KOFF)                                                              \
    do {                                                                            \
        _Pragma("unroll")                                                           \
        for (int p = 0; p < 4; ++p)                                                 \
            aReg[p] = av[p] ? *(const float4*)(Ab + (size_t)arow[p] * Kd + (KOFF) + ac4) \
                            : make_float4(0.f, 0.f, 0.f, 0.f);                      \
        _Pragma("unroll")                                                           \
        for (int p = 0; p < 2; ++p) {                                               \
            const float* brow = Bb + (size_t)((KOFF) + 2 * (bkp + p * 8)) * N + n0 + bc4; \
            bReg[2 * p] = *(const float4*)brow;                                     \
            bReg[2 * p + 1] = *(const float4*)(brow + N);                           \
        }                                                                           \
    } while (0)

#define STS_TILE(ST)                                                                \
    do {                                                                            \
        _Pragma("unroll")                                                           \
        for (int p = 0; p < 4; ++p) {                                               \
            int row = r0 + p * 32;                                                  \
            if (PREC == 0) {                                                        \
                uint32_t l0, l1;                                                    \
                uint32_t h0 = pack2bf(aReg[p].x, aReg[p].y, l0);                    \
                uint32_t h1 = pack2bf(aReg[p].z, aReg[p].w, l1);                    \
                *(uint2*)&Ah[ST][row * ALS + akp0] = make_uint2(h0, h1);            \
                *(uint2*)&Al[ST][row * ALS + akp0] = make_uint2(l0, l1);            \
            } else {                                                                \
                *(uint2*)&Ah[ST][row * ALS + akp0] =                                \
                    make_uint2(pack2h(aReg[p].x, aReg[p].y),                        \
                               pack2h(aReg[p].z, aReg[p].w));                       \
            }                                                                       \
        }                                                                           \
        _Pragma("unroll")                                                           \
        for (int p = 0; p < 2; ++p) {                                               \
            int kp = bkp + p * 8;                                                   \
            float4 v0 = bReg[2 * p], v1 = bReg[2 * p + 1];                          \
            if (PREC == 0) {                                                        \
                uint32_t h0, h1, h2, h3, l0, l1, l2, l3;                            \
                h0 = pack2bf(v0.x, v1.x, l0);                                       \
                h1 = pack2bf(v0.y, v1.y, l1);                                       \
                h2 = pack2bf(v0.z, v1.z, l2);                                       \
                h3 = pack2bf(v0.w, v1.w, l3);                                       \
                *(uint4*)&Bh[ST][kp * BPS + bc4] = make_uint4(h0, h1, h2, h3);      \
                *(uint4*)&Bl[ST][kp * BPS + bc4] = make_uint4(l0, l1, l2, l3);      \
            } else {                                                                \
                *(uint4*)&Bh[ST][kp * BPS + bc4] = make_uint4(                      \
                    pack2h(v0.x, v1.x), pack2h(v0.y, v1.y),                         \
                    pack2h(v0.z, v1.z), pack2h(v0.w, v1.w));                        \
            }                                                                       \
        }                                                                           \
    } while (0)

    LDG_TILE(0);
    STS_TILE(0);
    __syncthreads();

    const int nTiles = Kd >> 5;
    for (int t = 0; t < nTiles; ++t) {
        const int cur = t & 1, nxt = cur ^ 1;
        const uint32_t aOff = (uint32_t)cur * (128 * ALS * 4);
        if (t + 1 < nTiles) LDG_TILE((t + 1) << 5);
#pragma unroll
        for (int s = 0; s < 2; ++s) {
            const int kpb = s * 8;
            uint32_t ah[4][4];
#pragma unroll
            for (int mt = 0; mt < 4; ++mt) {
                uint32_t addr = ahBase + aOff + ((laneA + mt * 16 * ALS + kpb) << 2);
                LDSM4(ah[mt][0], ah[mt][1], ah[mt][2], ah[mt][3], addr);
            }
            uint32_t bh[4][2];
#pragma unroll
            for (int nt = 0; nt < 4; ++nt) {
                int n = warp_n + nt * 8 + gr;
                bh[nt][0] = Bh[cur][(kpb + gc) * BPS + n];
                bh[nt][1] = Bh[cur][(kpb + gc + 4) * BPS + n];
            }
            if (PREC == 0) {
                uint32_t al[4][4], bl[4][2];
#pragma unroll
                for (int mt = 0; mt < 4; ++mt) {
                    uint32_t addr = alBase + aOff + ((laneA + mt * 16 * ALS + kpb) << 2);
                    LDSM4(al[mt][0], al[mt][1], al[mt][2], al[mt][3], addr);
                }
#pragma unroll
                for (int nt = 0; nt < 4; ++nt) {
                    int n = warp_n + nt * 8 + gr;
                    bl[nt][0] = Bl[cur][(kpb + gc) * BPS + n];
                    bl[nt][1] = Bl[cur][(kpb + gc + 4) * BPS + n];
                }
#pragma unroll
                for (int mt = 0; mt < 4; ++mt)
#pragma unroll
                    for (int nt = 0; nt < 4; ++nt) {
                        float* c = acc[mt][nt];
                        MMA_BF16(c[0], c[1], c[2], c[3],
                                 ah[mt][0], ah[mt][1], ah[mt][2], ah[mt][3],
                                 bl[nt][0], bl[nt][1]);
                        MMA_BF16(c[0], c[1], c[2], c[3],
                                 al[mt][0], al[mt][1], al[mt][2], al[mt][3],
                                 bh[nt][0], bh[nt][1]);
                        MMA_BF16(c[0], c[1], c[2], c[3],
                                 ah[mt][0], ah[mt][1], ah[mt][2], ah[mt][3],
                                 bh[nt][0], bh[nt][1]);
                    }
            } else {
#pragma unroll
                for (int mt = 0; mt < 4; ++mt)
#pragma unroll
                    for (int nt = 0; nt < 4; ++nt) {
                        float* c = acc[mt][nt];
                        MMA_F16(c[0], c[1], c[2], c[3],
                                ah[mt][0], ah[mt][1], ah[mt][2], ah[mt][3],
                                bh[nt][0], bh[nt][1]);
                    }
            }
        }
        if (t + 1 < nTiles) {
            STS_TILE(nxt);
            __syncthreads();
        }
    }
#undef LDG_TILE
#undef STS_TILE

#pragma unroll
    for (int mt = 0; mt < 4; ++mt) {
#pragma unroll
        for (int rr = 0; rr < 2; ++rr) {
            int rg = m0 + warp_m + mt * 16 + gr + rr * 8;
            if (rg >= Mcur) continue;
            if (EPI == 3) {
                int t2 = tokb[rg];
                float w = wt[e * T_TOK + rg];
                float* outr = Cm0 + (size_t)t2 * N;
#pragma unroll
                for (int nt = 0; nt < 4; ++nt) {
                    int cb = n0 + warp_n + nt * 8 + gc * 2;
                    atomicAdd(&outr[cb], acc[mt][nt][rr * 2] * w);
                    atomicAdd(&outr[cb + 1], acc[mt][nt][rr * 2 + 1] * w);
                }
            } else {
#pragma unroll
                for (int nt = 0; nt < 4; ++nt) {
                    int cb = n0 + warp_n + nt * 8 + gc * 2;
                    float v0 = acc[mt][nt][rr * 2], v1 = acc[mt][nt][rr * 2 + 1];
                    if (EPI == 0) { v0 += bsel[cb]; v1 += bsel[cb + 1]; }
                    if (EPI == 1) {
                        const float* rrow = res + (size_t)rg * N;
                        v0 += rrow[cb]; v1 += rrow[cb + 1];
                    }
                    *(float2*)(Cb + (size_t)rg * N + cb) = make_float2(v0, v1);
                }
            }
        }
    }
}

// ---------------- RoPE: table computed inline per token block, f32 apply ----------------
__global__ void rope_apply_kernel(float* __restrict__ q, float* __restrict__ k,
                                  const int* __restrict__ pos) {
    int t = blockIdx.x, tid = threadIdx.x;
    __shared__ float cs[64], sn[64];
    if (tid < 64) {
        float p = (float)pos[t];
        float invf = (float)exp(-(double)tid * (13.815510557964274 / 64.0));
        float fr = p * invf;
        double d = (double)fr;
        double n = rint(d * 0.15915494309189535);
        float r = (float)(d - n * 6.283185307179586);
        float s, c;
        sincosf(r, &s, &c);
        cs[tid] = c;
        sn[tid] = s;
    }
    __syncthreads();
    for (int idx = tid; idx < (N_H + N_KVH) * 64; idx += 256) {
        int h = idx >> 6, i = idx & 63;
        float* b = (h < N_H) ? (q + ((size_t)t * N_H + h) * HD)
                             : (k + ((size_t)t * N_KVH + (h - N_H)) * HD);
        float c = cs[i], s = sn[i];
        float x1 = b[i], x2 = b[i + 64];
        b[i] = x1 * c - x2 * s;
        b[i + 64] = x2 * c + x1 * s;
    }
}

// ---------------- flash attention v5 (bf16x3, ldmatrix) ----------------
#define QLS 68
#define PLS 36
#define VPS 132
#define SST 68
__global__ void __launch_bounds__(256)
flash5_kernel(const float* __restrict__ q, const float* __restrict__ k,
              const float* __restrict__ v, float* __restrict__ o) {
    extern __shared__ uint32_t sm5[];
    uint32_t* Qh = sm5;
    uint32_t* Ql = Qh + 64 * QLS;
    uint32_t* Kh = Ql + 64 * QLS;
    uint32_t* Kl = Kh + 64 * QLS;
    float* Ss = (float*)(Kl + 64 * QLS);
    uint32_t* Ph = (uint32_t*)(Ss + 64 * SST);
    uint32_t* Pl = Ph + 64 * PLS;
    float* salpha = (float*)(Pl + 64 * PLS);
    const int tid = threadIdx.x;
    const int lane = tid & 31, warp = tid >> 5;
    const int gr = lane >> 2, gc = lane & 3;
    const int wms = (warp >> 1) * 16;
    const int wns = (warp & 1) * 32;
    const int wno = (warp & 1) * 64;
    const int sr = tid >> 2, sg = tid & 3;
    const int qt = blockIdx.x, head = blockIdx.y, kvh = head >> 2;
    const int qr0 = qt * 64;
    const float scale = 0.08838834764831845f;

    const uint32_t qhBase = smem_u32(Qh), qlBase = smem_u32(Ql);
    const uint32_t phBase = smem_u32(Ph), plBase = smem_u32(Pl);
    const int laneQ = (wms + (lane & 15)) * QLS + ((lane >> 4) << 2);
    const int laneP = (wms + (lane & 15)) * PLS + ((lane >> 4) << 2);

#pragma unroll
    for (int p = 0; p < 8; ++p) {
        int idx = tid + p * 256;
        int row = idx >> 5, c4 = (idx & 31) << 2;
        float4 vq = *(const float4*)(q + (size_t)(qr0 + row) * (N_H * HD) + head * HD + c4);
        int dp = c4 >> 1;
        uint32_t l0, l1;
        uint32_t h0 = pack2bf(vq.x, vq.y, l0);
        uint32_t h1 = pack2bf(vq.z, vq.w, l1);
        *(uint2*)&Qh[row * QLS + dp] = make_uint2(h0, h1);
        *(uint2*)&Ql[row * QLS + dp] = make_uint2(l0, l1);
    }
    float oacc[8][4];
#pragma unroll
    for (int nt = 0; nt < 8; ++nt)
#pragma unroll
        for (int r = 0; r < 4; ++r) oacc[nt][r] = 0.f;
    float mrow = -INFINITY, lrow = 0.f;

    for (int kt = 0; kt <= qt; ++kt) {
        const int kr0 = kt * 64;
        __syncthreads();
#pragma unroll
        for (int p = 0; p < 8; ++p) {
            int idx = tid + p * 256;
            int key = idx >> 5, c4 = (idx & 31) << 2;
            float4 vk = *(const float4*)(k + (size_t)(kr0 + key) * (N_KVH * HD) + kvh * HD + c4);
            int dp = c4 >> 1;
            uint32_t l0, l1;
            uint32_t h0 = pack2bf(vk.x, vk.y, l0);
            uint32_t h1 = pack2bf(vk.z, vk.w, l1);
            *(uint2*)&Kh[key * QLS + dp] = make_uint2(h0, h1);
            *(uint2*)&Kl[key * QLS + dp] = make_uint2(l0, l1);
        }
        __syncthreads();
        float sc[4][4];
#pragma unroll
        for (int nt = 0; nt < 4; ++nt)
#pragma unroll
            for (int r = 0; r < 4; ++r) sc[nt][r] = 0.f;
#pragma unroll
        for (int ks = 0; ks < 8; ++ks) {
            const int kpb = ks * 8;
            uint32_t ah[4], al[4];
            LDSM4(ah[0], ah[1], ah[2], ah[3], qhBase + ((laneQ + kpb) << 2));
            LDSM4(al[0], al[1], al[2], al[3], qlBase + ((laneQ + kpb) << 2));
#pragma unroll
            for (int nt = 0; nt < 4; ++nt) {
                int n = wns + nt * 8 + gr;
                uint32_t bh0 = Kh[n * QLS + kpb + gc];
                uint32_t bh1 = Kh[n * QLS + kpb + gc + 4];
                uint32_t bl0 = Kl[n * QLS + kpb + gc];
                uint32_t bl1 = Kl[n * QLS + kpb + gc + 4];
                float* c = sc[nt];
                MMA_BF16(c[0], c[1], c[2], c[3], ah[0], ah[1], ah[2], ah[3], bl0, bl1);
                MMA_BF16(c[0], c[1], c[2], c[3], al[0], al[1], al[2], al[3], bh0, bh1);
                MMA_BF16(c[0], c[1], c[2], c[3], ah[0], ah[1], ah[2], ah[3], bh0, bh1);
            }
        }
#pragma unroll
        for (int nt = 0; nt < 4; ++nt) {
            int cb = wns + nt * 8 + gc * 2;
            *(float2*)&Ss[(wms + gr) * SST + cb] = make_float2(sc[nt][0], sc[nt][1]);
            *(float2*)&Ss[(wms + gr + 8) * SST + cb] = make_float2(sc[nt][2], sc[nt][3]);
        }
        __syncthreads();
#pragma unroll
        for (int p = 0; p < 4; ++p) {
            int idx = tid + p * 256;
            int kp = idx >> 5, c4 = (idx & 31) << 2;
            const float* vrow = v + (size_t)(kr0 + 2 * kp) * (N_KVH * HD) + kvh * HD + c4;
            float4 v0 = *(const float4*)vrow;
            float4 v1 = *(const float4*)(vrow + N_KVH * HD);
            uint32_t h0, h1, h2, h3, l0, l1, l2, l3;
            h0 = pack2bf(v0.x, v1.x, l0);
            h1 = pack2bf(v0.y, v1.y, l1);
            h2 = pack2bf(v0.z, v1.z, l2);
            h3 = pack2bf(v0.w, v1.w, l3);
            *(uint4*)&Kh[kp * VPS + c4] = make_uint4(h0, h1, h2, h3);
            *(uint4*)&Kl[kp * VPS + c4] = make_uint4(l0, l1, l2, l3);
        }
        {
            float s[16];
#pragma unroll
            for (int jj = 0; jj < 16; ++jj) s[jj] = Ss[sr * SST + sg * 16 + jj];
            float mx = -INFINITY;
#pragma unroll
            for (int jj = 0; jj < 16; ++jj) {
                int col = kr0 + sg * 16 + jj;
                float sv = (col <= qr0 + sr) ? s[jj] * scale : -INFINITY;
                s[jj] = sv;
                mx = fmaxf(mx, sv);
            }
            mx = fmaxf(mx, __shfl_xor_sync(0xffffffffu, mx, 1));
            mx = fmaxf(mx, __shfl_xor_sync(0xffffffffu, mx, 2));
            float nm = fmaxf(mrow, mx);
            float rs = 0.f;
#pragma unroll
            for (int jj = 0; jj < 16; ++jj) {
                s[jj] = expf(s[jj] - nm);
                rs += s[jj];
            }
#pragma unroll
            for (int qq = 0; qq < 8; ++qq) {
                uint32_t lo;
                uint32_t hi = pack2bf(s[2 * qq], s[2 * qq + 1], lo);
                Ph[sr * PLS + sg * 8 + qq] = hi;
                Pl[sr * PLS + sg * 8 + qq] = lo;
            }
            rs += __shfl_xor_sync(0xffffffffu, rs, 1);
            rs += __shfl_xor_sync(0xffffffffu, rs, 2);
            float alpha = expf(mrow - nm);
            lrow = lrow * alpha + rs;
            mrow = nm;
            if (sg == 0) salpha[sr] = alpha;
        }
        __syncthreads();
        {
            float a0 = salpha[wms + gr], a1 = salpha[wms + gr + 8];
#pragma unroll
            for (int nt = 0; nt < 8; ++nt) {
                oacc[nt][0] *= a0; oacc[nt][1] *= a0;
                oacc[nt][2] *= a1; oacc[nt][3] *= a1;
            }
        }
#pragma unroll
        for (int ks = 0; ks < 4; ++ks) {
            const int kpb = ks * 8;
            uint32_t ah[4], al[4];
            LDSM4(ah[0], ah[1], ah[2], ah[3], phBase + ((laneP + kpb) << 2));
            LDSM4(al[0], al[1], al[2], al[3], plBase + ((laneP + kpb) << 2));
#pragma unroll
            for (int nt = 0; nt < 8; ++nt) {
                int n = wno + nt * 8 + gr;
                uint32_t bh0 = Kh[(kpb + gc) * VPS + n];
                uint32_t bh1 = Kh[(kpb + gc + 4) * VPS + n];
                uint32_t bl0 = Kl[(kpb + gc) * VPS + n];
                uint32_t bl1 = Kl[(kpb + gc + 4) * VPS + n];
                float* c = oacc[nt];
                MMA_BF16(c[0], c[1], c[2], c[3], ah[0], ah[1], ah[2], ah[3], bl0, bl1);
                MMA_BF16(c[0], c[1], c[2], c[3], al[0], al[1], al[2], al[3], bh0, bh1);
                MMA_BF16(c[0], c[1], c[2], c[3], ah[0], ah[1], ah[2], ah[3], bh0, bh1);
            }
        }
    }
    __syncthreads();
    if (sg == 0) salpha[sr] = 1.f / lrow;
    __syncthreads();
    float i0 = salpha[wms + gr], i1 = salpha[wms + gr + 8];
#pragma unroll
    for (int nt = 0; nt < 8; ++nt) {
        int cb = head * HD + wno + nt * 8 + gc * 2;
        *(float2*)(o + (size_t)(qr0 + wms + gr) * (N_H * HD) + cb) =
            make_float2(oacc[nt][0] * i0, oacc[nt][1] * i0);
        *(float2*)(o + (size_t)(qr0 + wms + gr + 8) * (N_H * HD) + cb) =
            make_float2(oacc[nt][2] * i1, oacc[nt][3] * i1);
    }
}

// ---------------- router (standalone; validated) ----------------
__global__ void router_kernel(const float* __restrict__ x, const float* __restrict__ gw,
                              int* __restrict__ cnt, int* __restrict__ tok,
                              float* __restrict__ wt) {
    int t = blockIdx.x;
    const float* xr = x + (size_t)t * D_DIM;
    float acc[8] = {0, 0, 0, 0, 0, 0, 0, 0};
    for (int d = threadIdx.x; d < D_DIM; d += 256) {
        float xv = xr[d];
        const float4* g4 = (const float4*)(gw + (size_t)d * N_E);
        float4 a = g4[0], b = g4[1];
        acc[0] = fmaf(xv, a.x, acc[0]); acc[1] = fmaf(xv, a.y, acc[1]);
        acc[2] = fmaf(xv, a.z, acc[2]); acc[3] = fmaf(xv, a.w, acc[3]);
        acc[4] = fmaf(xv, b.x, acc[4]); acc[5] = fmaf(xv, b.y, acc[5]);
        acc[6] = fmaf(xv, b.z, acc[6]); acc[7] = fmaf(xv, b.w, acc[7]);
    }
    __shared__ float smr[8][256];
#pragma unroll
    for (int e = 0; e < 8; ++e) smr[e][threadIdx.x] = acc[e];
    __syncthreads();
    for (int s = 128; s; s >>= 1) {
        if (threadIdx.x < s)
#pragma unroll
            for (int e = 0; e < 8; ++e) smr[e][threadIdx.x] += smr[e][threadIdx.x + s];
        __syncthreads();
    }
    if (threadIdx.x == 0) {
        float l[8], p[8];
        float mx = -1e30f;
#pragma unroll
        for (int e = 0; e < 8; ++e) { l[e] = smr[e][0]; mx = fmaxf(mx, l[e]); }
        float ssum = 0.f;
#pragma unroll
        for (int e = 0; e < 8; ++e) { p[e] = expf(l[e] - mx); ssum += p[e]; }
#pragma unroll
        for (int e = 0; e < 8; ++e) p[e] /= ssum;
        int i0 = 0; float p0 = p[0];
#pragma unroll
        for (int e = 1; e < 8; ++e) if (p[e] > p0) { p0 = p[e]; i0 = e; }
        int i1 = -1; float p1 = -1.f;
#pragma unroll
        for (int e = 0; e < 8; ++e) if (e != i0 && p[e] > p1) { p1 = p[e]; i1 = e; }
        float wn = p0 + p1;
        int pos = atomicAdd(&cnt[i0], 1);
        tok[i0 * T_TOK + pos] = t; wt[i0 * T_TOK + pos] = p0 / wn;
        pos = atomicAdd(&cnt[i1], 1);
        tok[i1 * T_TOK + pos] = t; wt[i1 * T_TOK + pos] = p1 / wn;
    }
}

// ---------------- silu(g)*u, only over active rows per expert ----------------
__global__ void silu_mul_kernel(float* __restrict__ g, const float* __restrict__ u,
                                const int* __restrict__ cnt) {
    int e = blockIdx.z;
    int row = blockIdx.y;
    if (row >= cnt[e]) return;
    size_t base = ((size_t)e * T_TOK + row) * I_DIM;
    int i = blockIdx.x * 256 + threadIdx.x;
    float4 gv = ((const float4*)(g + base))[i];
    float4 uv = ((const float4*)(u + base))[i];
    gv.x = gv.x / (1.f + __expf(-gv.x)) * uv.x;
    gv.y = gv.y / (1.f + __expf(-gv.y)) * uv.y;
    gv.z = gv.z / (1.f + __expf(-gv.z)) * uv.z;
    gv.w = gv.w / (1.f + __expf(-gv.w)) * uv.w;
    ((float4*)(g + base))[i] = gv;
}

// ---------------- launch ----------------
extern "C" void kernel_launch(void* const* d_in, const int* in_sizes, int n_in,
                              void* d_out, int out_size) {
    const float* hidden = (const float*)d_in[0];
    const int* positions = (const int*)d_in[1];
    const float* ln1 = (const float*)d_in[2];
    const float* ln2 = (const float*)d_in[3];
    const float* wq = (const float*)d_in[4];
    const float* bq = (const float*)d_in[5];
    const float* wk = (const float*)d_in[6];
    const float* bk = (const float*)d_in[7];
    const float* wv = (const float*)d_in[8];
    const float* bv = (const float*)d_in[9];
    const float* wo = (const float*)d_in[10];
    const float* gate_w = (const float*)d_in[11];
    const float* w_gate = (const float*)d_in[12];
    const float* w_up = (const float*)d_in[13];
    const float* w_down = (const float*)d_in[14];
    float* out = (float*)d_out;

    float *xnorm, *q, *k, *v, *attn, *x2, *gbuf, *ubuf, *wt;
    int *cnt, *tok;
    cudaGetSymbolAddress((void**)&xnorm, g_xnorm);
    cudaGetSymbolAddress((void**)&q, g_q);
    cudaGetSymbolAddress((void**)&k, g_k);
    cudaGetSymbolAddress((void**)&v, g_v);
    cudaGetSymbolAddress((void**)&attn, g_attn);
    cudaGetSymbolAddress((void**)&x2, g_x2);
    cudaGetSymbolAddress((void**)&gbuf, g_gbuf);
    cudaGetSymbolAddress((void**)&ubuf, g_ubuf);
    cudaGetSymbolAddress((void**)&cnt, g_cnt);
    cudaGetSymbolAddress((void**)&tok, g_tok);
    cudaGetSymbolAddress((void**)&wt, g_wt);

    const int smem_f5 = (4 * 64 * QLS + 64 * SST + 2 * 64 * PLS + 64) * 4;
    cudaFuncSetAttribute(flash5_kernel, cudaFuncAttributeMaxDynamicSharedMemorySize, smem_f5);

    // 1) RMSNorm 1
    rmsnorm_kernel<<<T_TOK, 256>>>(hidden, ln1, xnorm);
    // 2) fused QKV projection (+bias): bf16x3
    tgemm_kernel<0, false, 3, 0><<<dim3(24, 16, 1), 256>>>(
        xnorm, wq, wk, wv, q, k, v, bq, bk, bv,
        T_TOK, D_DIM, 2048, 512, 512, 16, 4,
        nullptr, nullptr, nullptr, nullptr, 0, 0, 0);
    // 3) RoPE apply (table computed inline, one block per token)
    rope_apply_kernel<<<T_TOK, 256>>>(q, k, positions);
    // 4) attention (bf16x3, ldmatrix)
    flash5_kernel<<<dim3(T_TOK / 64, N_H), 256, smem_f5>>>(q, k, v, attn);
    // 5) output proj + residual: bf16x3
    tgemm_kernel<1, false, 1, 0><<<dim3(16, 16, 1), 256>>>(
        attn, wo, nullptr, nullptr, out, nullptr, nullptr, nullptr, nullptr, nullptr,
        T_TOK, 2048, 2048, 0, 0, 16, 0,
        hidden, nullptr, nullptr, nullptr, 0, 0, 0);
    // 6) RMSNorm 2
    rmsnorm_kernel<<<T_TOK, 256>>>(out, ln2, x2);
    // 7) router
    cudaMemsetAsync(cnt, 0, N_E * sizeof(int));
    router_kernel<<<T_TOK, 256>>>(x2, gate_w, cnt, tok, wt);
    // 8) expert gate+up fused: fp16 single-MMA
    tgemm_kernel<2, true, 2, 1><<<dim3(16, 16, N_E), 256>>>(
        x2, w_gate, w_up, nullptr, gbuf, ubuf, nullptr, nullptr, nullptr, nullptr,
        0, D_DIM, 1024, 1024, 0, 8, 8,
        nullptr, cnt, tok, nullptr, 0, (long)D_DIM * I_DIM, (long)T_TOK * I_DIM);
    // 9) silu(g)*u on active rows only
    silu_mul_kernel<<<dim3(1, T_TOK, N_E), 256>>>(gbuf, ubuf, cnt);
    // 10) expert down GEMM: fp16 single-MMA, scatter *weight into d_out
    tgemm_kernel<3, false, 1, 1><<<dim3(16, 16, N_E), 256>>>(
        gbuf, w_down, nullptr, nullptr, out, nullptr, nullptr, nullptr, nullptr, nullptr,
        0, I_DIM, 2048, 0, 0, 16, 0,
        nullptr, cnt, tok, wt, (long)T_TOK * I_DIM, (long)I_DIM * D_DIM, 0);
}